// round 15
// baseline (speedup 1.0000x reference)
#include <cuda_runtime.h>
#include <cuda_fp16.h>

// ---------------- problem constants ----------------
#define NU   8039
#define NI   32770
#define NB   4771
#define NTOT (NU + NI + NB)        // 45580
#define EMB  32
#define NNZ  2000000
#define BATCH 2048
#define KB   100
#define EPSF    1e-8f
#define L2NORMF 1e-5f

#define SLOTS 128                  // bucket capacity per node (mean degree ~44)

// ---------------- static device scratch ----------------
// Counters rely on the invariant "zeroed on entry": statics are zero-initialized
// at load, and every execution re-zeroes them in k_score's tail, so the
// correctness run, capture, and each graph replay all see zeros.
__device__ int            g_cde[NTOT];            // in-degree counters (cols)
__device__ int            g_cdv[NTOT];            // out-degree counters (rows)
__device__ unsigned short g_adjA[NTOT * SLOTS];   // per col c: rows r   (pass 1)
__device__ unsigned short g_adjB[NTOT * SLOTS];   // per row r: cols c   (pass 2)
__device__ __align__(128) __half g_z[NTOT * EMB];   // x * dvi   (fp16, 64B/row)
__device__ __align__(128) __half g_u[NTOT * EMB];   // pass-1 result * dei (fp16)
__device__ __align__(128) float  g_emb[NTOT * EMB]; // final all_embeds (fp32)

// ---------------- kernels ----------------

// build both bucket adjacency lists, 4 edges per thread (R5 proven form)
__global__ void k_build(const int4* __restrict__ rows4, const int4* __restrict__ cols4) {
    int e = blockIdx.x * blockDim.x + threadIdx.x;
    if (e < NNZ / 4) {
        int4 r = __ldg(rows4 + e);
        int4 c = __ldg(cols4 + e);
        #pragma unroll
        for (int j = 0; j < 4; j++) {
            int rr = (j == 0) ? r.x : (j == 1) ? r.y : (j == 2) ? r.z : r.w;
            int cc = (j == 0) ? c.x : (j == 1) ? c.y : (j == 2) ? c.z : c.w;
            int pA = atomicAdd(&g_cde[cc], 1);
            if (pA < SLOTS) g_adjA[cc * SLOTS + pA] = (unsigned short)rr;
            int pB = atomicAdd(&g_cdv[rr], 1);
            if (pB < SLOTS) g_adjB[rr * SLOTS + pB] = (unsigned short)cc;
        }
    }
    cudaTriggerProgrammaticLaunchCompletion();
}

// z = x * dvi (half storage); x (pure input) prefetched BEFORE the PDL sync,
// only dvi (build output) read after. thread = (n, q), q in [0,8)
__global__ void k_makez(const float* __restrict__ uf, const float* __restrict__ itf,
                        const float* __restrict__ bf) {
    int i = blockIdx.x * blockDim.x + threadIdx.x;
    int n = i >> 3, q = i & 7;
    float4 x = make_float4(0.f, 0.f, 0.f, 0.f);
    if (i < NTOT * 8) {                           // pre-sync: input load
        const float4* src;
        if (n < NU)            src = (const float4*)(uf)  + n * 8 + q;
        else if (n < NU + NI)  src = (const float4*)(itf) + (n - NU) * 8 + q;
        else                   src = (const float4*)(bf)  + (n - NU - NI) * 8 + q;
        x = __ldg(src);
    }
    cudaGridDependencySynchronize();              // wait: cdv from k_build
    if (i < NTOT * 8) {
        float dvi = 1.0f / (sqrtf((float)g_cdv[n]) + EPSF);
        __half2 h0 = __floats2half2_rn(x.x * dvi, x.y * dvi);
        __half2 h1 = __floats2half2_rn(x.z * dvi, x.w * dvi);
        uint2 p;
        p.x = *reinterpret_cast<unsigned*>(&h0);
        p.y = *reinterpret_cast<unsigned*>(&h1);
        ((uint2*)g_z)[i] = p;
    }
    cudaTriggerProgrammaticLaunchCompletion();
}

// gather core with PRELOADED per-lane adjacency (4 chunks of 32 entries in
// registers; indices distributed via shfl). 4 groups x 8 lanes, 8 neighbor
// rows in flight, half2 accumulation per 32-chunk, fp32 flush between.
__device__ __forceinline__ float4 gather_pre(const unsigned* __restrict__ v,
                                             const uint2* __restrict__ tbl,
                                             int cnt, int g, int sub) {
    float4 facc = make_float4(0.f, 0.f, 0.f, 0.f);
    #pragma unroll
    for (int ch = 0; ch < 4; ch++) {
        int cb = ch * 32;
        if (cb >= cnt) break;                     // warp-uniform
        unsigned vc = v[ch];
        __half2 a0 = __float2half2_rn(0.f), a1 = a0, b0 = a0, b1 = a0;
        #pragma unroll
        for (int it = 0; it < 4; it++) {
            int base = cb + it * 8;
            int i0 = base + g;
            int i1 = base + 4 + g;
            unsigned r0 = __shfl_sync(0xffffffffu, vc, it * 8 + g);
            unsigned r1 = __shfl_sync(0xffffffffu, vc, it * 8 + 4 + g);
            if (i0 < cnt) {
                uint2 p = __ldg(tbl + r0 * 8 + sub);
                a0 = __hadd2(a0, *reinterpret_cast<__half2*>(&p.x));
                a1 = __hadd2(a1, *reinterpret_cast<__half2*>(&p.y));
            }
            if (i1 < cnt) {
                uint2 p = __ldg(tbl + r1 * 8 + sub);
                b0 = __hadd2(b0, *reinterpret_cast<__half2*>(&p.x));
                b1 = __hadd2(b1, *reinterpret_cast<__half2*>(&p.y));
            }
        }
        float2 f0 = __half22float2(__hadd2(a0, b0));
        float2 f1 = __half22float2(__hadd2(a1, b1));
        facc.x += f0.x; facc.y += f0.y; facc.z += f1.x; facc.w += f1.y;
    }
    // combine the 4 groups (lanes differing in bits 3,4)
    #pragma unroll
    for (int o = 8; o <= 16; o <<= 1) {
        facc.x += __shfl_xor_sync(0xffffffffu, facc.x, o);
        facc.y += __shfl_xor_sync(0xffffffffu, facc.y, o);
        facc.z += __shfl_xor_sync(0xffffffffu, facc.z, o);
        facc.w += __shfl_xor_sync(0xffffffffu, facc.w, o);
    }
    return facc;
}

// pass 1: u[n] = dei[n] * sum_{r in adjA[n]} z[r].
// Pre-sync: cde + adjA preload (build output — complete two PDL hops back,
// visible transitively). Post-sync: z gather only.
__global__ void k_pass1(float* __restrict__ loss_out) {
    if (blockIdx.x == 0 && threadIdx.x == 0) *loss_out = 0.0f;
    int n = blockIdx.x * 8 + (threadIdx.x >> 5);
    int lane = threadIdx.x & 31;
    int g = lane >> 3, sub = lane & 7;
    int cntRaw = 0;
    unsigned v[4];
    if (n < NTOT) {
        cntRaw = g_cde[n];
        const unsigned short* adj = g_adjA + n * SLOTS;
        #pragma unroll
        for (int ch = 0; ch < 4; ch++) v[ch] = adj[ch * 32 + lane];   // always in-bounds
    }
    cudaGridDependencySynchronize();              // wait: z from makez
    if (n < NTOT) {
        int cnt = cntRaw < SLOTS ? cntRaw : SLOTS;
        float4 acc = gather_pre(v, (const uint2*)g_z, cnt, g, sub);
        if (lane < 8) {
            float s = 1.0f / (sqrtf((float)cntRaw) + EPSF);   // dei
            __half2 h0 = __floats2half2_rn(acc.x * s, acc.y * s);
            __half2 h1 = __floats2half2_rn(acc.z * s, acc.w * s);
            uint2 p;
            p.x = *reinterpret_cast<unsigned*>(&h0);
            p.y = *reinterpret_cast<unsigned*>(&h1);
            ((uint2*)g_u)[n * 8 + sub] = p;
        }
    }
    cudaTriggerProgrammaticLaunchCompletion();
}

// pass 2 fused with final embed + loss.
// Pre-sync: cdv + adjB preload + x input load. Post-sync: u gather only.
// loss via block reduce + ONE atomic per block (per-warp same-address atomics
// serialize on the LTS atomic ALU — measured in R11).
__global__ void k_pass2(const float* __restrict__ uf, const float* __restrict__ itf,
                        const float* __restrict__ bf, float* __restrict__ loss_out) {
    __shared__ float sred[8];
    int n = blockIdx.x * 8 + (threadIdx.x >> 5);
    int lane = threadIdx.x & 31, w = threadIdx.x >> 5;
    int g = lane >> 3, sub = lane & 7;
    int cntRaw = 0;
    unsigned v[4];
    float4 x = make_float4(0.f, 0.f, 0.f, 0.f);
    if (n < NTOT) {
        cntRaw = g_cdv[n];
        const unsigned short* adj = g_adjB + n * SLOTS;
        #pragma unroll
        for (int ch = 0; ch < 4; ch++) v[ch] = adj[ch * 32 + lane];
        if (lane < 8) {
            const float4* src;
            if (n < NU)            src = (const float4*)(uf)  + n * 8 + sub;
            else if (n < NU + NI)  src = (const float4*)(itf) + (n - NU) * 8 + sub;
            else                   src = (const float4*)(bf)  + (n - NU - NI) * 8 + sub;
            x = __ldg(src);
        }
    }
    cudaGridDependencySynchronize();              // wait: u from pass1
    float sq = 0.0f;
    if (n < NTOT) {
        int cnt = cntRaw < SLOTS ? cntRaw : SLOTS;
        float4 acc = gather_pre(v, (const uint2*)g_u, cnt, g, sub);
        if (lane < 8) {
            float dvi = 1.0f / (sqrtf((float)cntRaw) + EPSF);
            float s = dvi * (1.0f / 3.0f);
            float4 emb;
            emb.x = 0.5f * x.x + acc.x * s;
            emb.y = 0.5f * x.y + acc.y * s;
            emb.z = 0.5f * x.z + acc.z * s;
            emb.w = 0.5f * x.w + acc.w * s;
            ((float4*)g_emb)[n * 8 + sub] = emb;
            sq = emb.x * emb.x + emb.y * emb.y + emb.z * emb.z + emb.w * emb.w;
        }
    }
    #pragma unroll
    for (int o = 16; o; o >>= 1) sq += __shfl_xor_sync(0xffffffffu, sq, o);
    if (lane == 0) sred[w] = sq;
    __syncthreads();
    if (threadIdx.x == 0) {
        float s = 0.0f;
        #pragma unroll
        for (int k = 0; k < 8; k++) s += sred[k];
        atomicAdd(loss_out, s * L2NORMF);
    }
    cudaTriggerProgrammaticLaunchCompletion();
}

// scoring: block per batch row, 128 threads; 8 lanes per bundle (float4/lane).
// Pre-sync: all index inputs prefetched. Post-sync: emb reads only.
// Tail: re-zero the degree counters so the NEXT execution (replay) starts clean.
__global__ void k_score(const int* __restrict__ users, const int* __restrict__ bundles,
                        const float* __restrict__ ubound,
                        float* __restrict__ pred, float* __restrict__ bound) {
    int b = blockIdx.x;
    int t = threadIdx.x;           // 128 threads
    int lane = t & 31, w = t >> 5;
    int g = lane >> 3, sub = lane & 7;
    int uidx = __ldg(&users[b]);
    int bi[7];
    #pragma unroll
    for (int it = 0; it < 7; it++) {
        int k = it * 16 + w * 4 + g;
        bi[it] = (k < KB) ? __ldg(&bundles[b * KB + k]) : 0;
    }
    float4 ub = make_float4(0.f, 0.f, 0.f, 0.f);
    if (t < 8) ub = __ldg((const float4*)ubound + t);
    cudaGridDependencySynchronize();              // wait: emb from pass2
    const float4* __restrict__ emb4 = (const float4*)g_emb;
    float4 ue4 = emb4[uidx * 8 + sub];            // L1 broadcast across groups/warps
    #pragma unroll
    for (int it = 0; it < 7; it++) {
        int k = it * 16 + w * 4 + g;
        if (k < KB) {
            float4 be = emb4[(NU + NI + bi[it]) * 8 + sub];
            float p = ue4.x * be.x + ue4.y * be.y + ue4.z * be.z + ue4.w * be.w;
            #pragma unroll
            for (int o = 1; o <= 4; o <<= 1) p += __shfl_xor_sync(0xffffffffu, p, o);
            if (sub == 0) pred[b * KB + k] = p;
        }
    }
    if (t < 8) {   // first group of warp 0 computes the bound
        float p = ue4.x * ub.x + ue4.y * ub.y + ue4.z * ub.z + ue4.w * ub.w;
        #pragma unroll
        for (int o = 1; o <= 4; o <<= 1) p += __shfl_xor_sync(0x000000ffu, p, o);
        if (t == 0) bound[b] = p;
    }
    // counter re-zero for next execution (2048*128 threads > 45580)
    int zi = b * 128 + t;
    if (zi < NTOT) { g_cde[zi] = 0; g_cdv[zi] = 0; }
}

// ---------------- launch ----------------
// PDL chain: consumers pre-stage while the producer drains and do their
// independent loads BEFORE cudaGridDependencySynchronize(). All launches are
// kernel nodes (graph-capturable); work per call is identical (deterministic).
template <typename F, typename... Args>
static inline void launch_pdl(F kern, int grid, int block, Args... args) {
    cudaLaunchConfig_t cfg = {};
    cfg.gridDim = dim3(grid, 1, 1);
    cfg.blockDim = dim3(block, 1, 1);
    cfg.stream = 0;
    cudaLaunchAttribute attr[1];
    attr[0].id = cudaLaunchAttributeProgrammaticStreamSerialization;
    attr[0].val.programmaticStreamSerializationAllowed = 1;
    cfg.attrs = attr;
    cfg.numAttrs = 1;
    cudaLaunchKernelEx(&cfg, kern, args...);
}

extern "C" void kernel_launch(void* const* d_in, const int* in_sizes, int n_in,
                              void* d_out, int out_size) {
    const float* uf      = (const float*)d_in[0];
    const float* itf     = (const float*)d_in[1];
    const float* bf      = (const float*)d_in[2];
    const float* ubound  = (const float*)d_in[3];
    const int*   rows    = (const int*)d_in[4];
    const int*   cols    = (const int*)d_in[5];
    const int*   users   = (const int*)d_in[6];
    const int*   bundles = (const int*)d_in[7];

    float* out   = (float*)d_out;
    float* pred  = out;                       // BATCH*KB
    float* bound = out + BATCH * KB;          // BATCH
    float* loss  = out + BATCH * KB + BATCH;  // 1

    const int T = 256;
    const int passBlocks = (NTOT + 7) / 8;    // 8 warps (nodes) per 256-thread block

    // first kernel: normal launch
    k_build<<<(NNZ / 4 + T - 1) / T, T>>>((const int4*)rows, (const int4*)cols);
    // dependent chain: PDL
    launch_pdl(k_makez, (NTOT * 8 + T - 1) / T, T, uf, itf, bf);
    launch_pdl(k_pass1, passBlocks, T, loss);
    launch_pdl(k_pass2, passBlocks, T, uf, itf, bf, loss);
    launch_pdl(k_score, BATCH, 128, users, bundles, ubound, pred, bound);
}

// round 16
// speedup vs baseline: 1.0825x; 1.0825x over previous
#include <cuda_runtime.h>
#include <cuda_fp16.h>

// ---------------- problem constants ----------------
#define NU   8039
#define NI   32770
#define NB   4771
#define NTOT (NU + NI + NB)        // 45580
#define EMB  32
#define NNZ  2000000
#define BATCH 2048
#define KB   100
#define EPSF    1e-8f
#define L2NORMF 1e-5f

#define SLOTS 128                  // bucket capacity per node (mean degree ~44)

// ---------------- static device scratch ----------------
// Counters rely on the invariant "zeroed on entry": statics are zero-initialized
// at load, and every execution re-zeroes them in k_score's tail, so the
// correctness run, capture, and each graph replay all see zeros.
__device__ int            g_cde[NTOT];            // in-degree counters (cols)
__device__ int            g_cdv[NTOT];            // out-degree counters (rows)
__device__ unsigned short g_adjA[NTOT * SLOTS];   // per col c: rows r   (pass 1)
__device__ unsigned short g_adjB[NTOT * SLOTS];   // per row r: cols c   (pass 2)
__device__ __align__(128) __half g_z[NTOT * EMB];   // x * dvi   (fp16, 64B/row)
__device__ __align__(128) __half g_u[NTOT * EMB];   // pass-1 result * dei (fp16)
__device__ __align__(128) float  g_emb[NTOT * EMB]; // final all_embeds (fp32)

// ---------------- kernels ----------------

// build both bucket adjacency lists, 4 edges per thread (R5 proven form)
__global__ void k_build(const int4* __restrict__ rows4, const int4* __restrict__ cols4) {
    int e = blockIdx.x * blockDim.x + threadIdx.x;
    if (e < NNZ / 4) {
        int4 r = __ldg(rows4 + e);
        int4 c = __ldg(cols4 + e);
        #pragma unroll
        for (int j = 0; j < 4; j++) {
            int rr = (j == 0) ? r.x : (j == 1) ? r.y : (j == 2) ? r.z : r.w;
            int cc = (j == 0) ? c.x : (j == 1) ? c.y : (j == 2) ? c.z : c.w;
            int pA = atomicAdd(&g_cde[cc], 1);
            if (pA < SLOTS) g_adjA[cc * SLOTS + pA] = (unsigned short)rr;
            int pB = atomicAdd(&g_cdv[rr], 1);
            if (pB < SLOTS) g_adjB[rr * SLOTS + pB] = (unsigned short)cc;
        }
    }
    cudaTriggerProgrammaticLaunchCompletion();
}

// z = x * dvi (half storage); x (pure input) prefetched BEFORE the PDL sync,
// only dvi (build output) read after. 16-reg kernel — no occupancy risk.
__global__ void k_makez(const float* __restrict__ uf, const float* __restrict__ itf,
                        const float* __restrict__ bf) {
    int i = blockIdx.x * blockDim.x + threadIdx.x;
    int n = i >> 3, q = i & 7;
    float4 x = make_float4(0.f, 0.f, 0.f, 0.f);
    if (i < NTOT * 8) {                           // pre-sync: input load
        const float4* src;
        if (n < NU)            src = (const float4*)(uf)  + n * 8 + q;
        else if (n < NU + NI)  src = (const float4*)(itf) + (n - NU) * 8 + q;
        else                   src = (const float4*)(bf)  + (n - NU - NI) * 8 + q;
        x = __ldg(src);
    }
    cudaGridDependencySynchronize();              // wait: cdv from k_build
    if (i < NTOT * 8) {
        float dvi = 1.0f / (sqrtf((float)g_cdv[n]) + EPSF);
        __half2 h0 = __floats2half2_rn(x.x * dvi, x.y * dvi);
        __half2 h1 = __floats2half2_rn(x.z * dvi, x.w * dvi);
        uint2 p;
        p.x = *reinterpret_cast<unsigned*>(&h0);
        p.y = *reinterpret_cast<unsigned*>(&h1);
        ((uint2*)g_z)[i] = p;
    }
    cudaTriggerProgrammaticLaunchCompletion();
}

// gather core (R5/R13 proven layout): warp-per-node, 4 groups x 8 lanes, 8
// neighbor rows in flight, half2 accumulation per 32-chunk, fp32 flush between.
// Adjacency read in-loop (register-lean: 32 regs, occ ~87%).
__device__ __forceinline__ float4 gather_half(const unsigned short* __restrict__ adj,
                                              const uint2* __restrict__ tbl,
                                              int cnt, int g, int sub) {
    float4 facc = make_float4(0.f, 0.f, 0.f, 0.f);
    for (int cb = 0; cb < cnt; cb += 32) {
        __half2 a0 = __float2half2_rn(0.f), a1 = a0, b0 = a0, b1 = a0;
        #pragma unroll
        for (int it = 0; it < 4; it++) {
            int base = cb + it * 8;
            int i0 = base + g;
            int i1 = base + 4 + g;
            if (i0 < cnt) {
                unsigned r = adj[i0];
                uint2 p = __ldg(tbl + r * 8 + sub);
                a0 = __hadd2(a0, *reinterpret_cast<__half2*>(&p.x));
                a1 = __hadd2(a1, *reinterpret_cast<__half2*>(&p.y));
            }
            if (i1 < cnt) {
                unsigned r = adj[i1];
                uint2 p = __ldg(tbl + r * 8 + sub);
                b0 = __hadd2(b0, *reinterpret_cast<__half2*>(&p.x));
                b1 = __hadd2(b1, *reinterpret_cast<__half2*>(&p.y));
            }
        }
        float2 f0 = __half22float2(__hadd2(a0, b0));
        float2 f1 = __half22float2(__hadd2(a1, b1));
        facc.x += f0.x; facc.y += f0.y; facc.z += f1.x; facc.w += f1.y;
    }
    // combine the 4 groups (lanes differing in bits 3,4)
    #pragma unroll
    for (int o = 8; o <= 16; o <<= 1) {
        facc.x += __shfl_xor_sync(0xffffffffu, facc.x, o);
        facc.y += __shfl_xor_sync(0xffffffffu, facc.y, o);
        facc.z += __shfl_xor_sync(0xffffffffu, facc.z, o);
        facc.w += __shfl_xor_sync(0xffffffffu, facc.w, o);
    }
    return facc;
}

// pass 1: u[n] = dei[n] * sum_{r in adjA[n]} z[r]; dei in-register from cde.
// Also zeroes the loss slot (pass1 fully precedes pass2's atomics).
__global__ void k_pass1(float* __restrict__ loss_out) {
    cudaGridDependencySynchronize();            // wait: adjA/cde + z
    if (blockIdx.x == 0 && threadIdx.x == 0) *loss_out = 0.0f;
    int n = blockIdx.x * 8 + (threadIdx.x >> 5);
    if (n < NTOT) {
        int lane = threadIdx.x & 31;
        int g = lane >> 3, sub = lane & 7;
        int cntRaw = g_cde[n];
        int cnt = cntRaw < SLOTS ? cntRaw : SLOTS;
        float4 acc = gather_half(g_adjA + n * SLOTS, (const uint2*)g_z, cnt, g, sub);
        if (lane < 8) {
            float s = 1.0f / (sqrtf((float)cntRaw) + EPSF);   // dei
            __half2 h0 = __floats2half2_rn(acc.x * s, acc.y * s);
            __half2 h1 = __floats2half2_rn(acc.z * s, acc.w * s);
            uint2 p;
            p.x = *reinterpret_cast<unsigned*>(&h0);
            p.y = *reinterpret_cast<unsigned*>(&h1);
            ((uint2*)g_u)[n * 8 + sub] = p;
        }
    }
    cudaTriggerProgrammaticLaunchCompletion();
}

// pass 2 fused with final embed + loss; dvi in-register from cdv.
// loss via block reduce (smem) + ONE atomic per block (per-warp same-address
// atomics serialize on the LTS atomic ALU — measured in R11).
__global__ void k_pass2(const float* __restrict__ uf, const float* __restrict__ itf,
                        const float* __restrict__ bf, float* __restrict__ loss_out) {
    cudaGridDependencySynchronize();            // wait: u from pass1
    __shared__ float sred[8];
    int n = blockIdx.x * 8 + (threadIdx.x >> 5);
    int lane = threadIdx.x & 31, w = threadIdx.x >> 5;
    int g = lane >> 3, sub = lane & 7;
    float sq = 0.0f;
    if (n < NTOT) {
        int cntRaw = g_cdv[n];
        int cnt = cntRaw < SLOTS ? cntRaw : SLOTS;
        float4 acc = gather_half(g_adjB + n * SLOTS, (const uint2*)g_u, cnt, g, sub);
        if (lane < 8) {
            const float4* src;
            if (n < NU)            src = (const float4*)(uf)  + n * 8 + sub;
            else if (n < NU + NI)  src = (const float4*)(itf) + (n - NU) * 8 + sub;
            else                   src = (const float4*)(bf)  + (n - NU - NI) * 8 + sub;
            float4 x = __ldg(src);
            float dvi = 1.0f / (sqrtf((float)cntRaw) + EPSF);
            float s = dvi * (1.0f / 3.0f);
            float4 emb;
            emb.x = 0.5f * x.x + acc.x * s;
            emb.y = 0.5f * x.y + acc.y * s;
            emb.z = 0.5f * x.z + acc.z * s;
            emb.w = 0.5f * x.w + acc.w * s;
            ((float4*)g_emb)[n * 8 + sub] = emb;
            sq = emb.x * emb.x + emb.y * emb.y + emb.z * emb.z + emb.w * emb.w;
        }
    }
    #pragma unroll
    for (int o = 16; o; o >>= 1) sq += __shfl_xor_sync(0xffffffffu, sq, o);
    if (lane == 0) sred[w] = sq;
    __syncthreads();
    if (threadIdx.x == 0) {
        float s = 0.0f;
        #pragma unroll
        for (int k = 0; k < 8; k++) s += sred[k];
        atomicAdd(loss_out, s * L2NORMF);
    }
    cudaTriggerProgrammaticLaunchCompletion();
}

// scoring: block per batch row, 128 threads; 8 lanes per bundle (float4/lane).
// Pre-sync: all index inputs prefetched (pure inputs; ~10 extra regs on a
// 128-thread block — no occupancy constraint at this size). Post-sync: emb only.
// Tail: re-zero the degree counters so the NEXT execution (replay) starts clean.
__global__ void k_score(const int* __restrict__ users, const int* __restrict__ bundles,
                        const float* __restrict__ ubound,
                        float* __restrict__ pred, float* __restrict__ bound) {
    int b = blockIdx.x;
    int t = threadIdx.x;           // 128 threads
    int lane = t & 31, w = t >> 5;
    int g = lane >> 3, sub = lane & 7;
    int uidx = __ldg(&users[b]);
    int bi[7];
    #pragma unroll
    for (int it = 0; it < 7; it++) {
        int k = it * 16 + w * 4 + g;
        bi[it] = (k < KB) ? __ldg(&bundles[b * KB + k]) : 0;
    }
    float4 ub = make_float4(0.f, 0.f, 0.f, 0.f);
    if (t < 8) ub = __ldg((const float4*)ubound + t);
    cudaGridDependencySynchronize();              // wait: emb from pass2
    const float4* __restrict__ emb4 = (const float4*)g_emb;
    float4 ue4 = emb4[uidx * 8 + sub];            // L1 broadcast across groups/warps
    #pragma unroll
    for (int it = 0; it < 7; it++) {
        int k = it * 16 + w * 4 + g;
        if (k < KB) {
            float4 be = emb4[(NU + NI + bi[it]) * 8 + sub];
            float p = ue4.x * be.x + ue4.y * be.y + ue4.z * be.z + ue4.w * be.w;
            #pragma unroll
            for (int o = 1; o <= 4; o <<= 1) p += __shfl_xor_sync(0xffffffffu, p, o);
            if (sub == 0) pred[b * KB + k] = p;
        }
    }
    if (t < 8) {   // first group of warp 0 computes the bound
        float p = ue4.x * ub.x + ue4.y * ub.y + ue4.z * ub.z + ue4.w * ub.w;
        #pragma unroll
        for (int o = 1; o <= 4; o <<= 1) p += __shfl_xor_sync(0x000000ffu, p, o);
        if (t == 0) bound[b] = p;
    }
    // counter re-zero for next execution (2048*128 threads > 45580)
    int zi = b * 128 + t;
    if (zi < NTOT) { g_cde[zi] = 0; g_cdv[zi] = 0; }
}

// ---------------- launch ----------------
// PDL chain (proven R13 structure). All launches are kernel nodes
// (graph-capturable); work per call is identical (deterministic).
template <typename F, typename... Args>
static inline void launch_pdl(F kern, int grid, int block, Args... args) {
    cudaLaunchConfig_t cfg = {};
    cfg.gridDim = dim3(grid, 1, 1);
    cfg.blockDim = dim3(block, 1, 1);
    cfg.stream = 0;
    cudaLaunchAttribute attr[1];
    attr[0].id = cudaLaunchAttributeProgrammaticStreamSerialization;
    attr[0].val.programmaticStreamSerializationAllowed = 1;
    cfg.attrs = attr;
    cfg.numAttrs = 1;
    cudaLaunchKernelEx(&cfg, kern, args...);
}

extern "C" void kernel_launch(void* const* d_in, const int* in_sizes, int n_in,
                              void* d_out, int out_size) {
    const float* uf      = (const float*)d_in[0];
    const float* itf     = (const float*)d_in[1];
    const float* bf      = (const float*)d_in[2];
    const float* ubound  = (const float*)d_in[3];
    const int*   rows    = (const int*)d_in[4];
    const int*   cols    = (const int*)d_in[5];
    const int*   users   = (const int*)d_in[6];
    const int*   bundles = (const int*)d_in[7];

    float* out   = (float*)d_out;
    float* pred  = out;                       // BATCH*KB
    float* bound = out + BATCH * KB;          // BATCH
    float* loss  = out + BATCH * KB + BATCH;  // 1

    const int T = 256;
    const int passBlocks = (NTOT + 7) / 8;    // 8 warps (nodes) per 256-thread block

    // first kernel: normal launch
    k_build<<<(NNZ / 4 + T - 1) / T, T>>>((const int4*)rows, (const int4*)cols);
    // dependent chain: PDL
    launch_pdl(k_makez, (NTOT * 8 + T - 1) / T, T, uf, itf, bf);
    launch_pdl(k_pass1, passBlocks, T, loss);
    launch_pdl(k_pass2, passBlocks, T, uf, itf, bf, loss);
    launch_pdl(k_score, BATCH, 128, users, bundles, ubound, pred, bound);
}